// round 14
// baseline (speedup 1.0000x reference)
#include <cuda_runtime.h>
#include <cuda_fp16.h>
#include <math.h>
#include <stdint.h>

typedef unsigned int u32;

#define B_    2
#define N_    1024
#define HID   2048
#define H_    32
#define D_    64
#define HKV   8
#define CHUNK 64
#define NC    16
#define TOK   (B_ * N_)
#define QDIM  (H_ * D_)
#define KDIM  (HKV * D_)
#define KVD   1024
#define PAD   65

// ---------------- fp32 scratch ----------------
__device__ float g_q[TOK * QDIM];
__device__ float g_kv[TOK * KVD];
__device__ float g_ql[TOK * QDIM];
__device__ float g_kl[TOK * KDIM];
__device__ float g_beta[TOK * KDIM];
__device__ float g_obase[TOK * QDIM];
__device__ float g_W[B_ * H_ * NC * 64 * 64];
__device__ float g_U[B_ * H_ * NC * 64 * 64];
__device__ float g_A[B_ * H_ * NC * 64 * 64];
__device__ float g_inv[B_ * H_ * N_];
// fp16 scratch
__device__ __half g_hsh[TOK * HID];
__device__ __half g_hsl[TOK * HID];
__device__ __half g_wq[HID * QDIM];
__device__ __half g_wkv[HID * KVD];
__device__ __half g_wo[QDIM * HID];
__device__ __half g_oxh[TOK * QDIM];
// pre-converted fp16 operands for base attention
__device__ __half g_q16h[TOK * QDIM];
__device__ __half g_q16l[TOK * QDIM];
__device__ __half g_kv16[TOK * KVD];

// ---------------- fused split/convert ----------------
#define SEG0 (TOK * HID)
#define SEG1 (HID * QDIM)
#define SEG2 (HID * KDIM)
#define SEG3 (HID * KDIM)
#define SEG4 (QDIM * HID)
__global__ void split_all(const float* __restrict__ hs, const float* __restrict__ Wq,
                          const float* __restrict__ Wk, const float* __restrict__ Wv,
                          const float* __restrict__ Wo) {
    int i = blockIdx.x * 256 + threadIdx.x;
    if (i < SEG0) {
        float x = hs[i];
        __half hv = __float2half(x);
        g_hsh[i] = hv;
        g_hsl[i] = __float2half(x - __half2float(hv));
    } else if (i < SEG0 + SEG1) {
        int j = i - SEG0;
        g_wq[j] = __float2half(Wq[j]);
    } else if (i < SEG0 + SEG1 + SEG2) {
        int j = i - SEG0 - SEG1;
        int r = j >> 9, c = j & 511;
        g_wkv[(size_t)r * KVD + c] = __float2half(Wk[j]);
    } else if (i < SEG0 + SEG1 + SEG2 + SEG3) {
        int j = i - SEG0 - SEG1 - SEG2;
        int r = j >> 9, c = j & 511;
        g_wkv[(size_t)r * KVD + 512 + c] = __float2half(Wv[j]);
    } else if (i < SEG0 + SEG1 + SEG2 + SEG3 + SEG4) {
        int j = i - SEG0 - SEG1 - SEG2 - SEG3;
        g_wo[j] = __float2half(Wo[j]);
    }
}

// ---------------- mma wrappers ----------------
__device__ __forceinline__ void ldsm_x4(u32* r, u32 addr) {
    asm volatile("ldmatrix.sync.aligned.m8n8.x4.shared.b16 {%0,%1,%2,%3}, [%4];"
                 : "=r"(r[0]), "=r"(r[1]), "=r"(r[2]), "=r"(r[3]) : "r"(addr));
}
__device__ __forceinline__ void ldsm_x4t(u32* r, u32 addr) {
    asm volatile("ldmatrix.sync.aligned.m8n8.x4.trans.shared.b16 {%0,%1,%2,%3}, [%4];"
                 : "=r"(r[0]), "=r"(r[1]), "=r"(r[2]), "=r"(r[3]) : "r"(addr));
}
__device__ __forceinline__ void mma_f16(float* c, const u32* a, const u32* b) {
    asm volatile(
        "mma.sync.aligned.m16n8k16.row.col.f32.f16.f16.f32 "
        "{%0,%1,%2,%3}, {%4,%5,%6,%7}, {%8,%9}, {%0,%1,%2,%3};"
        : "+f"(c[0]), "+f"(c[1]), "+f"(c[2]), "+f"(c[3])
        : "r"(a[0]), "r"(a[1]), "r"(a[2]), "r"(a[3]), "r"(b[0]), "r"(b[1]));
}
__device__ __forceinline__ u32 packh2(float a, float b) {
    __half2 h = __floats2half2_rn(a, b);
    return *(u32*)&h;
}
__device__ __forceinline__ void cp16(u32 dst, const void* src) {
    asm volatile("cp.async.cg.shared.global [%0], [%1], 16;" :: "r"(dst), "l"(src));
}
// fast exp on the FMA pipe: rel err < 4e-6
__device__ __forceinline__ float fexp(float x) {
    float y = x * 1.4426950408889634f;
    float t = y + 12582912.0f;
    float fl = t - 12582912.0f;
    float f = y - fl;
    float p = 1.3333558e-3f;
    p = p * f + 9.6181291e-3f;
    p = p * f + 5.5504109e-2f;
    p = p * f + 2.4022651e-1f;
    p = p * f + 6.9314718e-1f;
    p = p * f + 1.0f;
    int i = (int)fl;
    return p * __int_as_float((i + 127) << 23);
}

// ---------------- hgemm (cp.async double-buffered): C ~= AhB (+AlB if useAl) -----
// optional fp16 outputs: Ch = half(v*hscale), Cl = residual (if non-null)
#define ASTRIDE 40
#define BSTRIDE 136
#define ASZB (128 * ASTRIDE * 2)
#define BSZB (32 * BSTRIDE * 2)
#define HG_SMEM (4 * ASZB + 2 * BSZB)
__global__ void __launch_bounds__(256) hgemm(
    const __half* __restrict__ Ah, const __half* __restrict__ Al,
    const __half* __restrict__ B,
    float* __restrict__ C, __half* __restrict__ Ch, __half* __restrict__ Cl,
    float hscale, int N, int K, int useAl) {
    extern __shared__ __half hsm[];
    const u32 smem0 = (u32)__cvta_generic_to_shared(hsm);

    const int tid = threadIdx.x;
    const int lane = tid & 31;
    const int wid = tid >> 5;
    const int warp_m = wid & 3;
    const int warp_n = wid >> 2;
    const int cRow = blockIdx.y * 128;
    const int cCol = blockIdx.x * 128;

    float acc[2][8][4];
#pragma unroll
    for (int mt = 0; mt < 2; ++mt) {
#pragma unroll
        for (int nt = 0; nt < 8; ++nt) {
#pragma unroll
            for (int i = 0; i < 4; ++i) acc[mt][nt][i] = 0.f;
        }
    }

    const int T = K >> 5;
    {
        const int kb = 0;
#pragma unroll
        for (int i = 0; i < 2; ++i) {
            int q = tid + i * 256;
            int ar = q >> 2;
            int ac = (q & 3) * 8;
            cp16(smem0 + (u32)((ar * ASTRIDE + ac) * 2),
                 Ah + (size_t)(cRow + ar) * K + kb + ac);
            if (useAl) {
                cp16(smem0 + 2 * ASZB + (u32)((ar * ASTRIDE + ac) * 2),
                     Al + (size_t)(cRow + ar) * K + kb + ac);
            }
            int br = q >> 4;
            int bc = (q & 15) * 8;
            cp16(smem0 + 4 * ASZB + (u32)((br * BSTRIDE + bc) * 2),
                 B + (size_t)(kb + br) * N + cCol + bc);
        }
        asm volatile("cp.async.commit_group;" ::: "memory");
    }

    for (int kt = 0; kt < T; ++kt) {
        const int cur = kt & 1;
        if (kt + 1 < T) {
            const int nxt = cur ^ 1;
            const int kb = (kt + 1) * 32;
#pragma unroll
            for (int i = 0; i < 2; ++i) {
                int q = tid + i * 256;
                int ar = q >> 2;
                int ac = (q & 3) * 8;
                cp16(smem0 + (u32)(nxt * ASZB) + (u32)((ar * ASTRIDE + ac) * 2),
                     Ah + (size_t)(cRow + ar) * K + kb + ac);
                if (useAl) {
                    cp16(smem0 + 2 * ASZB + (u32)(nxt * ASZB) + (u32)((ar * ASTRIDE + ac) * 2),
                         Al + (size_t)(cRow + ar) * K + kb + ac);
                }
                int br = q >> 4;
                int bc = (q & 15) * 8;
                cp16(smem0 + 4 * ASZB + (u32)(nxt * BSZB) + (u32)((br * BSTRIDE + bc) * 2),
                     B + (size_t)(kb + br) * N + cCol + bc);
            }
            asm volatile("cp.async.commit_group;" ::: "memory");
            asm volatile("cp.async.wait_group 1;" ::: "memory");
        } else {
            asm volatile("cp.async.wait_group 0;" ::: "memory");
        }
        __syncthreads();

        const u32 aH = smem0 + (u32)(cur * ASZB);
        const u32 aL = smem0 + 2 * ASZB + (u32)(cur * ASZB);
        const u32 bB = smem0 + 4 * ASZB + (u32)(cur * BSZB);
#pragma unroll
        for (int kk = 0; kk < 32; kk += 16) {
            u32 a_h[2][4];
            u32 a_l[2][4];
            u32 b_f[8][2];
#pragma unroll
            for (int mt = 0; mt < 2; ++mt) {
                int row = warp_m * 32 + mt * 16 + (lane & 15);
                u32 off = (u32)((row * ASTRIDE + kk + (lane >> 4) * 8) * 2);
                ldsm_x4(a_h[mt], aH + off);
                if (useAl) {
                    ldsm_x4(a_l[mt], aL + off);
                }
            }
#pragma unroll
            for (int p = 0; p < 4; ++p) {
                int colbase = warp_n * 64 + p * 16;
                int krow = kk + (lane & 7) + ((lane >> 3) & 1) * 8;
                int col = colbase + ((lane >> 4) & 1) * 8;
                u32 off = (u32)((krow * BSTRIDE + col) * 2);
                u32 r[4];
                ldsm_x4t(r, bB + off);
                b_f[2 * p][0] = r[0];
                b_f[2 * p][1] = r[1];
                b_f[2 * p + 1][0] = r[2];
                b_f[2 * p + 1][1] = r[3];
            }
#pragma unroll
            for (int mt = 0; mt < 2; ++mt) {
#pragma unroll
                for (int nt = 0; nt < 8; ++nt) {
                    mma_f16(acc[mt][nt], a_h[mt], b_f[nt]);
                    if (useAl) {
                        mma_f16(acc[mt][nt], a_l[mt], b_f[nt]);
                    }
                }
            }
        }
        __syncthreads();
    }

#pragma unroll
    for (int mt = 0; mt < 2; ++mt) {
#pragma unroll
        for (int nt = 0; nt < 8; ++nt) {
            int r = cRow + warp_m * 32 + mt * 16 + (lane >> 2);
            int c = cCol + warp_n * 64 + nt * 8 + (lane & 3) * 2;
            float v0 = acc[mt][nt][0];
            float v1 = acc[mt][nt][1];
            float v2 = acc[mt][nt][2];
            float v3 = acc[mt][nt][3];
            *(float2*)&C[(size_t)r * N + c] = make_float2(v0, v1);
            *(float2*)&C[(size_t)(r + 8) * N + c] = make_float2(v2, v3);
            if (Ch) {
                float s0 = v0 * hscale;
                float s1 = v1 * hscale;
                float s2 = v2 * hscale;
                float s3 = v3 * hscale;
                __half2 h01 = __floats2half2_rn(s0, s1);
                __half2 h23 = __floats2half2_rn(s2, s3);
                *(__half2*)&Ch[(size_t)r * N + c] = h01;
                *(__half2*)&Ch[(size_t)(r + 8) * N + c] = h23;
                if (Cl) {
                    __half2 l01 = __floats2half2_rn(s0 - __low2float(h01),
                                                    s1 - __high2float(h01));
                    __half2 l23 = __floats2half2_rn(s2 - __low2float(h23),
                                                    s3 - __high2float(h23));
                    *(__half2*)&Cl[(size_t)r * N + c] = l01;
                    *(__half2*)&Cl[(size_t)(r + 8) * N + c] = l23;
                }
            }
        }
    }
}

// ------------- feature kernel -------------
__global__ void feat_kernel() {
    const int wg = (blockIdx.x * blockDim.x + threadIdx.x) >> 5;
    const int lane = threadIdx.x & 31;
    if (wg < TOK * H_) {
        const float* src = g_q + (size_t)wg * 64;
        float x0 = src[lane];
        float x1 = src[lane + 32];
        float m = fmaxf(x0, x1);
#pragma unroll
        for (int o = 16; o; o >>= 1) m = fmaxf(m, __shfl_xor_sync(0xffffffffu, m, o));
        float e0 = __expf(x0 - m);
        float e1 = __expf(x1 - m);
        float s = e0 + e1;
#pragma unroll
        for (int o = 16; o; o >>= 1) s += __shfl_xor_sync(0xffffffffu, s, o);
        float inv = 1.f / s;
        float* dst = g_ql + (size_t)wg * 64;
        dst[lane] = e0 * inv;
        dst[lane + 32] = e1 * inv;
    } else if (wg < TOK * H_ + TOK * HKV) {
        const int r = wg - TOK * H_;
        const float* src = g_kv + (size_t)(r >> 3) * KVD + (r & 7) * 64;
        float x0 = src[lane];
        float x1 = src[lane + 32];
        float m = fmaxf(x0, x1);
#pragma unroll
        for (int o = 16; o; o >>= 1) m = fmaxf(m, __shfl_xor_sync(0xffffffffu, m, o));
        float e0 = __expf(x0 - m);
        float e1 = __expf(x1 - m);
        float s = e0 + e1;
#pragma unroll
        for (int o = 16; o; o >>= 1) s += __shfl_xor_sync(0xffffffffu, s, o);
        float inv = 1.f / s;
        float* dst = g_kl + (size_t)r * 64;
        dst[lane] = e0 * inv;
        dst[lane + 32] = e1 * inv;
        float b0 = (fminf(x0, 0.f) - log1pf(__expf(-fabsf(x0)))) * 0.0625f;
        float b1 = (fminf(x1, 0.f) - log1pf(__expf(-fabsf(x1)))) * 0.0625f;
        float* bd = g_beta + (size_t)r * 64;
        bd[lane] = b0;
        bd[lane + 32] = b1;
    }
}

// --------- delta stage 1 (grid = 1024) ---------
__global__ void delta_stage1() {
    extern __shared__ float sm[];
    float* Kc = sm;
    float* W = Kc + 64 * PAD;
    float* U = W + 64 * PAD;
    float* L = U + 64 * PAD;
    float* Q = L + 64 * PAD;

    const int tid = threadIdx.x;
    const int blk = blockIdx.x;
    const int bh = blk >> 4;
    const int ch = blk & 15;
    const int b = bh >> 5;
    const int h = bh & 31;
    const int hkv = h >> 2;
    const int e = tid & 63;
    const int r0 = (tid >> 6) * 8;
    const int n0 = ch * CHUNK;

    for (int idx = tid; idx < 4096; idx += 512) {
        int c = idx >> 6;
        int d = idx & 63;
        int t = b * N_ + n0 + c;
        float kv = g_kl[(size_t)t * KDIM + hkv * 64 + d];
        float bt = g_beta[(size_t)t * KDIM + hkv * 64 + d];
        float vv = g_kv[(size_t)t * KVD + 512 + hkv * 64 + d];
        Kc[c * PAD + d] = kv;
        W[c * PAD + d] = kv * bt;
        U[c * PAD + d] = vv * bt;
        Q[c * PAD + d] = g_ql[(size_t)t * QDIM + h * 64 + d];
    }
    __syncthreads();

    {
        float acc[8];
#pragma unroll
        for (int i = 0; i < 8; ++i) acc[i] = 0.f;
        for (int d = 0; d < 64; ++d) {
            float kb = Kc[e * PAD + d];
#pragma unroll
            for (int i = 0; i < 8; ++i) acc[i] += W[(r0 + i) * PAD + d] * kb;
        }
#pragma unroll
        for (int i = 0; i < 8; ++i) {
            L[(r0 + i) * PAD + e] = (e < r0 + i) ? acc[i] : 0.f;
        }
    }
    __syncthreads();

    for (int j = 0; j < 63; ++j) {
        float uj = U[j * PAD + e];
        float wj = W[j * PAD + e];
        for (int i = j + 1 + (tid >> 6); i < 64; i += 8) {
            float lij = L[i * PAD + j];
            U[i * PAD + e] -= lij * uj;
            W[i * PAD + e] -= lij * wj;
        }
        __syncthreads();
    }

    {
        float acc[8];
#pragma unroll
        for (int i = 0; i < 8; ++i) acc[i] = 0.f;
        for (int d = 0; d < 64; ++d) {
            float kb = Kc[e * PAD + d];
#pragma unroll
            for (int i = 0; i < 8; ++i) acc[i] += Q[(r0 + i) * PAD + d] * kb;
        }
        float* Ao = g_A + (size_t)blk * 4096;
#pragma unroll
        for (int i = 0; i < 8; ++i) {
            Ao[(r0 + i) * 64 + e] = (e <= r0 + i) ? acc[i] : 0.f;
        }
    }
    {
        float* Wo_ = g_W + (size_t)blk * 4096;
        float* Uo_ = g_U + (size_t)blk * 4096;
#pragma unroll
        for (int i = 0; i < 8; ++i) {
            Wo_[(r0 + i) * 64 + e] = W[(r0 + i) * PAD + e];
            Uo_[(r0 + i) * 64 + e] = U[(r0 + i) * PAD + e];
        }
    }
}

// --------------- mma base causal attention, SINGLE pass, fp16 operands -----------
#define QST 72
#define EST 68
__global__ void __launch_bounds__(256) base_attn_mma(float* __restrict__ attnw) {
    extern __shared__ char smc[];
    __half* Qh = (__half*)smc;
    __half* Ql = Qh + 64 * QST;
    __half* Kt = Ql + 64 * QST;
    __half* Vt = Kt + 64 * QST;
    float* Et = (float*)(Vt + 64 * QST);
    float* rbuf = Et + 64 * EST;

    const int it = blockIdx.x;
    const int bh = blockIdx.y;
    const int b = bh >> 5;
    const int h = bh & 31;
    const int hkv = h >> 2;
    const int tid = threadIdx.x;
    const int lane = tid & 31;
    const int wid = tid >> 5;
    const int warp_m = wid & 3;
    const int warp_n = wid >> 2;
    const int m0 = warp_m * 16;
    const int jn0 = warp_n * 32;

    u32 sQh = (u32)__cvta_generic_to_shared(Qh);
    u32 sQl = (u32)__cvta_generic_to_shared(Ql);
    u32 sKt = (u32)__cvta_generic_to_shared(Kt);
    u32 sVt = (u32)__cvta_generic_to_shared(Vt);

    for (int idx = tid; idx < 512; idx += 256) {
        int r = idx >> 3;
        int d = (idx & 7) * 8;
        size_t gp = (size_t)(b * N_ + it * 64 + r) * QDIM + h * 64 + d;
        *(uint4*)&Qh[r * QST + d] = *(const uint4*)&g_q16h[gp];
        *(uint4*)&Ql[r * QST + d] = *(const uint4*)&g_q16l[gp];
    }
    __syncthreads();

    u32 qa_h[4][4];
    u32 qa_l[4][4];
#pragma unroll
    for (int ks = 0; ks < 4; ++ks) {
        u32 off = (u32)(((m0 + (lane & 15)) * QST + ks * 16 + (lane >> 4) * 8) * 2);
        ldsm_x4(qa_h[ks], sQh + off);
        ldsm_x4(qa_l[ks], sQl + off);
    }

    const int r_in0 = m0 + (lane >> 2);
    const int gr0 = it * 64 + r_in0;
    const int gr1 = gr0 + 8;

    float o[8][4];
#pragma unroll
    for (int nt = 0; nt < 8; ++nt) {
#pragma unroll
        for (int i = 0; i < 4; ++i) o[nt][i] = 0.f;
    }
    float rs0 = 0.f;
    float rs1 = 0.f;

    for (int jt = 0; jt <= it; ++jt) {
        __syncthreads();
        for (int idx = tid; idx < 512; idx += 256) {
            int r = idx >> 3;
            int d = (idx & 7) * 8;
            const __half* kvrow = g_kv16 + (size_t)(b * N_ + jt * 64 + r) * KVD + hkv * 64;
            *(uint4*)&Kt[r * QST + d] = *(const uint4*)(kvrow + d);
            *(uint4*)&Vt[r * QST + d] = *(const uint4*)(kvrow + 512 + d);
        }
        __syncthreads();

        float c[4][4];
#pragma unroll
        for (int nt = 0; nt < 4; ++nt) {
#pragma unroll
            for (int i = 0; i < 4; ++i) c[nt][i] = 0.f;
        }
#pragma unroll
        for (int ks = 0; ks < 4; ++ks) {
#pragma unroll
            for (int np = 0; np < 2; ++np) {
                u32 bf[4];
                u32 row = (u32)(jn0 + np * 16 + ((lane >> 4) & 1) * 8 + (lane & 7));
                u32 off = (u32)((row * QST + ks * 16 + ((lane >> 3) & 1) * 8) * 2);
                ldsm_x4(bf, sKt + off);
                mma_f16(c[2 * np], qa_h[ks], bf);
                mma_f16(c[2 * np], qa_l[ks], bf);
                mma_f16(c[2 * np + 1], qa_h[ks], bf + 2);
                mma_f16(c[2 * np + 1], qa_l[ks], bf + 2);
            }
        }

        const bool diag = (jt == it);
#pragma unroll
        for (int nt = 0; nt < 4; ++nt) {
            int col = jn0 + nt * 8 + (lane & 3) * 2;
            int gc = jt * 64 + col;
            float e00 = (!diag || gc <= gr0) ? fexp(c[nt][0] - 4.f) : 0.f;
            float e01 = (!diag || gc + 1 <= gr0) ? fexp(c[nt][1] - 4.f) : 0.f;
            float e10 = (!diag || gc <= gr1) ? fexp(c[nt][2] - 4.f) : 0.f;
            float e11 = (!diag || gc + 1 <= gr1) ? fexp(c[nt][3] - 4.f) : 0.f;
            rs0 += e00 + e01;
            rs1 += e10 + e11;
            c[nt][0] = e00;
            c[nt][1] = e01;
            c[nt][2] = e10;
            c[nt][3] = e11;
            Et[r_in0 * EST + col] = e00;
            Et[r_in0 * EST + col + 1] = e01;
            Et[(r_in0 + 8) * EST + col] = e10;
            Et[(r_in0 + 8) * EST + col + 1] = e11;
        }

        u32 pa[2][4];
#pragma unroll
        for (int kp = 0; kp < 2; ++kp) {
            pa[kp][0] = packh2(c[2 * kp][0], c[2 * kp][1]);
            pa[kp][1] = packh2(c[2 * kp][2], c[2 * kp][3]);
            pa[kp][2] = packh2(c[2 * kp + 1][0], c[2 * kp + 1][1]);
            pa[kp][3] = packh2(c[2 * kp + 1][2], c[2 * kp + 1][3]);
        }
#pragma unroll
        for (int kp = 0; kp < 2; ++kp) {
#pragma unroll
            for (int dp = 0; dp < 4; ++dp) {
                u32 bf[4];
                u32 krow = (u32)(jn0 + kp * 16 + (lane & 7) + ((lane >> 3) & 1) * 8);
                u32 off = (u32)((krow * QST + dp * 16 + ((lane >> 4) & 1) * 8) * 2);
                ldsm_x4t(bf, sVt + off);
                mma_f16(o[2 * dp], pa[kp], bf);
                mma_f16(o[2 * dp + 1], pa[kp], bf + 2);
            }
        }

        __syncthreads();
        if (attnw) {
#pragma unroll
            for (int rr = 0; rr < 4; ++rr) {
                int r = rr * 16 + (tid >> 4);
                int d = (tid & 15) * 4;
                *(float4*)&attnw[((size_t)bh * N_ + it * 64 + r) * N_ + jt * 64 + d] =
                    *(float4*)&Et[r * EST + d];
            }
        }
    }

    if (attnw) {
        float4 z4 = make_float4(0.f, 0.f, 0.f, 0.f);
        for (int jt = it + 1; jt < 16; ++jt) {
#pragma unroll
            for (int rr = 0; rr < 4; ++rr) {
                int r = rr * 16 + (tid >> 4);
                int d = (tid & 15) * 4;
                *(float4*)&attnw[((size_t)bh * N_ + it * 64 + r) * N_ + jt * 64 + d] = z4;
            }
        }
    }

    rs0 += __shfl_xor_sync(0xffffffffu, rs0, 1);
    rs0 += __shfl_xor_sync(0xffffffffu, rs0, 2);
    rs1 += __shfl_xor_sync(0xffffffffu, rs1, 1);
    rs1 += __shfl_xor_sync(0xffffffffu, rs1, 2);
    if ((lane & 3) == 0) {
        rbuf[warp_n * 64 + r_in0] = rs0;
        rbuf[warp_n * 64 + r_in0 + 8] = rs1;
    }
    __syncthreads();
    if (tid < 64) {
        float iv = 1.f / (rbuf[tid] + rbuf[64 + tid]);
        rbuf[tid] = iv;
        g_inv[(size_t)bh * N_ + it * 64 + tid] = iv;
    }
    __syncthreads();
    const float inv0 = rbuf[r_in0];
    const float inv1 = rbuf[r_in0 + 8];

    __syncthreads();
    if (warp_n == 1) {
#pragma unroll
        for (int nt = 0; nt < 8; ++nt) {
            int d = nt * 8 + (lane & 3) * 2;
            Et[r_in0 * EST + d] = o[nt][0];
            Et[r_in0 * EST + d + 1] = o[nt][1];
            Et[(r_in0 + 8) * EST + d] = o[nt][2];
            Et[(r_in0 + 8) * EST + d + 1] = o[nt][3];
        }
    }
    __syncthreads();
    if (warp_n == 0) {
#pragma unroll
        for (int nt = 0; nt < 8; ++nt) {
            int d = nt * 8 + (lane & 3) * 2;
            float v00 = (o[nt][0] + Et[r_in0 * EST + d]) * inv0;
            float v01 = (o[nt][1] + Et[r_in0 * EST + d + 1]) * inv0;
            float v10 = (o[nt][2] + Et[(r_in0 + 8) * EST + d]) * inv1;
            float v11 = (o[nt][3] + Et[(r_in0 + 8) * EST + d + 1]) * inv1;
            size_t p0 = (size_t)(b * N_ + it * 64 + r_in0) * QDIM + h * 64 + d;
            size_t p1 = (size_t)(b * N_ + it * 64 + r_in0 + 8) * QDIM + h * 64 + d;
            *(float2*)&g_obase[p0] = make_float2(v00, v01);
            *(float2*)&g_obase[p1] = make_float2(v10, v11);
        }
    }
}

// --------- renormalize attnw rows by g_inv (coalesced float4) ---------
__global__ void renorm_attn(float* __restrict__ attnw) {
    const int i = blockIdx.x;
    const int bh = blockIdx.y;
    const float iv = g_inv[(size_t)bh * N_ + i];
    float4* row = (float4*)&attnw[((size_t)bh * N_ + i) * N_];
    float4 v = row[threadIdx.x];
    v.x *= iv;
    v.y *= iv;
    v.z *= iv;
    v.w *= iv;
    row[threadIdx.x] = v;
}

// --------- delta stage 2 (grid = 64); epilogue fuses mix + fp16 convert ---------
__global__ void delta_stage2() {
    extern __shared__ float sm[];
    float* S = sm;
    float* W = S + 64 * PAD;
    float* U = W + 64 * PAD;
    float* A = U + 64 * PAD;
    float* Q = A + 64 * PAD;
    float* Kc = Q + 64 * PAD;

    const int tid = threadIdx.x;
    const int bh = blockIdx.x;
    const int b = bh >> 5;
    const int h = bh & 31;
    const int hkv = h >> 2;
    const int e = tid & 63;
    const int r0 = (tid >> 6) * 8;

    for (int idx = tid; idx < 4096; idx += 512) {
        S[(idx >> 6) * PAD + (idx & 63)] = 0.f;
    }
    __syncthreads();

    for (int ch = 0; ch < NC; ++ch) {
        const int n0 = ch * CHUNK;
        const size_t base = (size_t)(bh * NC + ch) * 4096;
        for (int idx = tid; idx < 4096; idx += 512) {
            int c = idx >> 6;
            int d = idx & 63;
            int t = b * N_ + n0 + c;
            W[c * PAD + d] = g_W[base + idx];
            U[c * PAD + d] = g_U[base + idx];
            A[c * PAD + d] = g_A[base + idx];
            Q[c * PAD + d] = g_ql[(size_t)t * QDIM + h * 64 + d];
            Kc[c * PAD + d] = g_kl[(size_t)t * KDIM + hkv * 64 + d];
        }
        __syncthreads();

        {
            float acc[8];
#pragma unroll
            for (int i = 0; i < 8; ++i) acc[i] = 0.f;
            for (int d = 0; d < 64; ++d) {
                float s = S[d * PAD + e];
#pragma unroll
                for (int i = 0; i < 8; ++i) acc[i] += W[(r0 + i) * PAD + d] * s;
            }
#pragma unroll
            for (int i = 0; i < 8; ++i) U[(r0 + i) * PAD + e] -= acc[i];
        }
        __syncthreads();

        {
            float acc[8];
#pragma unroll
            for (int i = 0; i < 8; ++i) acc[i] = 0.f;
            for (int d = 0; d < 64; ++d) {
                float s = S[d * PAD + e];
#pragma unroll
                for (int i = 0; i < 8; ++i) acc[i] += Q[(r0 + i) * PAD + d] * s;
            }
            for (int j = 0; j < 64; ++j) {
                float u = U[j * PAD + e];
#pragma unroll
                for (int i = 0; i < 8; ++i) acc[i] += A[(r0 + i) * PAD + j] * u;
            }
            // fused: mix with o_base (MAG=0.5) and convert to fp16 operand
#pragma unroll
            for (int i = 0; i < 8; ++i) {
                size_t idx = (size_t)(b * N_ + n0 + r0 + i) * QDIM + h * 64 + e;
                float x = 0.5f * acc[i] + 0.5f * g_obase[idx];
                g_oxh[idx] = __float2half(x);
            }
        }
        __syncthreads();

        {
            float acc[8];
#pragma unroll
            for (int i = 0; i < 8; ++i) acc[i] = 0.f;
            for (int c = 0; c < 64; ++c) {
                float u = U[c * PAD + e];
#pragma unroll
                for (int i = 0; i < 8; ++i) acc[i] += Kc[c * PAD + r0 + i] * u;
            }
#pragma unroll
            for (int i = 0; i < 8; ++i) S[(r0 + i) * PAD + e] += acc[i];
        }
        __syncthreads();
    }
}

// ------------------------------------ launch -------------------------------------
extern "C" void kernel_launch(void* const* d_in, const int* in_sizes, int n_in,
                              void* d_out, int out_size) {
    const float* hs = (const float*)d_in[0];
    const float* Wq = (const float*)d_in[1];
    const float* Wk = (const float*)d_in[2];
    const float* Wv = (const float*)d_in[3];
    const float* Wo = (const float*)d_in[4];
    float* out = (float*)d_out;

    const size_t out_elems = (size_t)TOK * QDIM;
    const size_t attn_elems = (size_t)B_ * H_ * N_ * N_;
    float* attnw = ((size_t)out_size >= out_elems + attn_elems) ? (out + out_elems)
                                                                : (float*)0;

    float* qp;
    float* kvp;
    __half* hshp; __half* hslp;
    __half* wqp;
    __half* wkvp;
    __half* wop;
    __half* oxhp;
    __half* q16hp; __half* q16lp; __half* kv16p;
    cudaGetSymbolAddress((void**)&qp, g_q);
    cudaGetSymbolAddress((void**)&kvp, g_kv);
    cudaGetSymbolAddress((void**)&hshp, g_hsh);
    cudaGetSymbolAddress((void**)&hslp, g_hsl);
    cudaGetSymbolAddress((void**)&wqp, g_wq);
    cudaGetSymbolAddress((void**)&wkvp, g_wkv);
    cudaGetSymbolAddress((void**)&wop, g_wo);
    cudaGetSymbolAddress((void**)&oxhp, g_oxh);
    cudaGetSymbolAddress((void**)&q16hp, g_q16h);
    cudaGetSymbolAddress((void**)&q16lp, g_q16l);
    cudaGetSymbolAddress((void**)&kv16p, g_kv16);

    cudaFuncSetAttribute(hgemm, cudaFuncAttributeMaxDynamicSharedMemorySize, HG_SMEM);
    cudaFuncSetAttribute(delta_stage1, cudaFuncAttributeMaxDynamicSharedMemorySize,
                         5 * 64 * PAD * (int)sizeof(float));
    cudaFuncSetAttribute(delta_stage2, cudaFuncAttributeMaxDynamicSharedMemorySize,
                         6 * 64 * PAD * (int)sizeof(float));
    const int ba_smem = 4 * 64 * QST * 2 + 64 * EST * 4 + 128 * 4;
    cudaFuncSetAttribute(base_attn_mma, cudaFuncAttributeMaxDynamicSharedMemorySize,
                         ba_smem);

    // 1: fused split/convert
    {
        const int total = SEG0 + SEG1 + SEG2 + SEG3 + SEG4;
        split_all<<<(total + 255) / 256, 256>>>(hs, Wq, Wk, Wv, Wo);
    }

    // 2-3: projections (+ fp16 side outputs for base attention), split-A
    hgemm<<<dim3(QDIM / 128, TOK / 128), 256, HG_SMEM>>>(
        hshp, hslp, wqp, qp, q16hp, q16lp, 0.125f, QDIM, HID, 1);
    hgemm<<<dim3(KVD / 128, TOK / 128), 256, HG_SMEM>>>(
        hshp, hslp, wkvp, kvp, kv16p, (__half*)0, 1.0f, KVD, HID, 1);

    // 4: feature maps + gate
    {
        const int total_warps = TOK * H_ + TOK * HKV;
        const int blocks = (total_warps * 32 + 255) / 256;
        feat_kernel<<<blocks, 256>>>();
    }

    // 5: delta stage 1
    delta_stage1<<<B_ * H_ * NC, 512, 5 * 64 * PAD * sizeof(float)>>>();

    // 6: base attention (single pass, fp16 operands)
    base_attn_mma<<<dim3(16, B_ * H_), 256, ba_smem>>>(attnw);

    // 7: renormalize attention weights
    if (attnw) {
        renorm_attn<<<dim3(N_, B_ * H_), 256>>>(attnw);
    }

    // 8: delta stage 2 (fuses mix + fp16 convert in epilogue)
    delta_stage2<<<B_ * H_, 512, 6 * 64 * PAD * sizeof(float)>>>();

    // 9: output projection (single-A fp16)
    hgemm<<<dim3(HID / 128, TOK / 128), 256, HG_SMEM>>>(
        oxhp, (__half*)0, wop, out, (__half*)0, (__half*)0, 1.0f, HID, QDIM, 0);
}

// round 15
// speedup vs baseline: 1.0409x; 1.0409x over previous
#include <cuda_runtime.h>
#include <cuda_fp16.h>
#include <math.h>
#include <stdint.h>

typedef unsigned int u32;

#define B_    2
#define N_    1024
#define HID   2048
#define H_    32
#define D_    64
#define HKV   8
#define CHUNK 64
#define NC    16
#define TOK   (B_ * N_)
#define QDIM  (H_ * D_)
#define KDIM  (HKV * D_)
#define KVD   1024
#define PAD   65

// ---------------- fp32 scratch ----------------
__device__ float g_q[TOK * QDIM];
__device__ float g_kv[TOK * KVD];
__device__ float g_ql[TOK * QDIM];
__device__ float g_kl[TOK * KDIM];
__device__ float g_beta[TOK * KDIM];
__device__ float g_olin[TOK * QDIM];
__device__ float g_obase[TOK * QDIM];
__device__ float g_W[B_ * H_ * NC * 64 * 64];
__device__ float g_U[B_ * H_ * NC * 64 * 64];
__device__ float g_A[B_ * H_ * NC * 64 * 64];
__device__ float g_inv[B_ * H_ * N_];
// fp16 scratch
__device__ __half g_hsh[TOK * HID];
__device__ __half g_hsl[TOK * HID];
__device__ __half g_wq[HID * QDIM];
__device__ __half g_wkv[HID * KVD];
__device__ __half g_wo[QDIM * HID];
__device__ __half g_oxh[TOK * QDIM];
// pre-converted fp16 operands for base attention
__device__ __half g_q16h[TOK * QDIM];
__device__ __half g_q16l[TOK * QDIM];
__device__ __half g_kv16[TOK * KVD];

// ---------------- fused split/convert ----------------
#define SEG0 (TOK * HID)
#define SEG1 (HID * QDIM)
#define SEG2 (HID * KDIM)
#define SEG3 (HID * KDIM)
#define SEG4 (QDIM * HID)
__global__ void split_all(const float* __restrict__ hs, const float* __restrict__ Wq,
                          const float* __restrict__ Wk, const float* __restrict__ Wv,
                          const float* __restrict__ Wo) {
    int i = blockIdx.x * 256 + threadIdx.x;
    if (i < SEG0) {
        float x = hs[i];
        __half hv = __float2half(x);
        g_hsh[i] = hv;
        g_hsl[i] = __float2half(x - __half2float(hv));
    } else if (i < SEG0 + SEG1) {
        int j = i - SEG0;
        g_wq[j] = __float2half(Wq[j]);
    } else if (i < SEG0 + SEG1 + SEG2) {
        int j = i - SEG0 - SEG1;
        int r = j >> 9, c = j & 511;
        g_wkv[(size_t)r * KVD + c] = __float2half(Wk[j]);
    } else if (i < SEG0 + SEG1 + SEG2 + SEG3) {
        int j = i - SEG0 - SEG1 - SEG2;
        int r = j >> 9, c = j & 511;
        g_wkv[(size_t)r * KVD + 512 + c] = __float2half(Wv[j]);
    } else if (i < SEG0 + SEG1 + SEG2 + SEG3 + SEG4) {
        int j = i - SEG0 - SEG1 - SEG2 - SEG3;
        g_wo[j] = __float2half(Wo[j]);
    }
}

// ---------------- mma wrappers ----------------
__device__ __forceinline__ void ldsm_x4(u32* r, u32 addr) {
    asm volatile("ldmatrix.sync.aligned.m8n8.x4.shared.b16 {%0,%1,%2,%3}, [%4];"
                 : "=r"(r[0]), "=r"(r[1]), "=r"(r[2]), "=r"(r[3]) : "r"(addr));
}
__device__ __forceinline__ void ldsm_x4t(u32* r, u32 addr) {
    asm volatile("ldmatrix.sync.aligned.m8n8.x4.trans.shared.b16 {%0,%1,%2,%3}, [%4];"
                 : "=r"(r[0]), "=r"(r[1]), "=r"(r[2]), "=r"(r[3]) : "r"(addr));
}
__device__ __forceinline__ void mma_f16(float* c, const u32* a, const u32* b) {
    asm volatile(
        "mma.sync.aligned.m16n8k16.row.col.f32.f16.f16.f32 "
        "{%0,%1,%2,%3}, {%4,%5,%6,%7}, {%8,%9}, {%0,%1,%2,%3};"
        : "+f"(c[0]), "+f"(c[1]), "+f"(c[2]), "+f"(c[3])
        : "r"(a[0]), "r"(a[1]), "r"(a[2]), "r"(a[3]), "r"(b[0]), "r"(b[1]));
}
__device__ __forceinline__ u32 packh2(float a, float b) {
    __half2 h = __floats2half2_rn(a, b);
    return *(u32*)&h;
}
__device__ __forceinline__ void cp16(u32 dst, const void* src) {
    asm volatile("cp.async.cg.shared.global [%0], [%1], 16;" :: "r"(dst), "l"(src));
}
// fast exp on the FMA pipe: rel err < 4e-6
__device__ __forceinline__ float fexp(float x) {
    float y = x * 1.4426950408889634f;
    float t = y + 12582912.0f;
    float fl = t - 12582912.0f;
    float f = y - fl;
    float p = 1.3333558e-3f;
    p = p * f + 9.6181291e-3f;
    p = p * f + 5.5504109e-2f;
    p = p * f + 2.4022651e-1f;
    p = p * f + 6.9314718e-1f;
    p = p * f + 1.0f;
    int i = (int)fl;
    return p * __int_as_float((i + 127) << 23);
}

// ---------------- hgemm (cp.async double-buffered): C ~= AhB (+AlB if useAl) -----
#define ASTRIDE 40
#define BSTRIDE 136
#define ASZB (128 * ASTRIDE * 2)
#define BSZB (32 * BSTRIDE * 2)
#define HG_SMEM (4 * ASZB + 2 * BSZB)
__global__ void __launch_bounds__(256) hgemm(
    const __half* __restrict__ Ah, const __half* __restrict__ Al,
    const __half* __restrict__ B,
    float* __restrict__ C, __half* __restrict__ Ch, __half* __restrict__ Cl,
    float hscale, int N, int K, int useAl) {
    extern __shared__ __half hsm[];
    const u32 smem0 = (u32)__cvta_generic_to_shared(hsm);

    const int tid = threadIdx.x;
    const int lane = tid & 31;
    const int wid = tid >> 5;
    const int warp_m = wid & 3;
    const int warp_n = wid >> 2;
    const int cRow = blockIdx.y * 128;
    const int cCol = blockIdx.x * 128;

    float acc[2][8][4];
#pragma unroll
    for (int mt = 0; mt < 2; ++mt) {
#pragma unroll
        for (int nt = 0; nt < 8; ++nt) {
#pragma unroll
            for (int i = 0; i < 4; ++i) acc[mt][nt][i] = 0.f;
        }
    }

    const int T = K >> 5;
    {
        const int kb = 0;
#pragma unroll
        for (int i = 0; i < 2; ++i) {
            int q = tid + i * 256;
            int ar = q >> 2;
            int ac = (q & 3) * 8;
            cp16(smem0 + (u32)((ar * ASTRIDE + ac) * 2),
                 Ah + (size_t)(cRow + ar) * K + kb + ac);
            if (useAl) {
                cp16(smem0 + 2 * ASZB + (u32)((ar * ASTRIDE + ac) * 2),
                     Al + (size_t)(cRow + ar) * K + kb + ac);
            }
            int br = q >> 4;
            int bc = (q & 15) * 8;
            cp16(smem0 + 4 * ASZB + (u32)((br * BSTRIDE + bc) * 2),
                 B + (size_t)(kb + br) * N + cCol + bc);
        }
        asm volatile("cp.async.commit_group;" ::: "memory");
    }

    for (int kt = 0; kt < T; ++kt) {
        const int cur = kt & 1;
        if (kt + 1 < T) {
            const int nxt = cur ^ 1;
            const int kb = (kt + 1) * 32;
#pragma unroll
            for (int i = 0; i < 2; ++i) {
                int q = tid + i * 256;
                int ar = q >> 2;
                int ac = (q & 3) * 8;
                cp16(smem0 + (u32)(nxt * ASZB) + (u32)((ar * ASTRIDE + ac) * 2),
                     Ah + (size_t)(cRow + ar) * K + kb + ac);
                if (useAl) {
                    cp16(smem0 + 2 * ASZB + (u32)(nxt * ASZB) + (u32)((ar * ASTRIDE + ac) * 2),
                         Al + (size_t)(cRow + ar) * K + kb + ac);
                }
                int br = q >> 4;
                int bc = (q & 15) * 8;
                cp16(smem0 + 4 * ASZB + (u32)(nxt * BSZB) + (u32)((br * BSTRIDE + bc) * 2),
                     B + (size_t)(kb + br) * N + cCol + bc);
            }
            asm volatile("cp.async.commit_group;" ::: "memory");
            asm volatile("cp.async.wait_group 1;" ::: "memory");
        } else {
            asm volatile("cp.async.wait_group 0;" ::: "memory");
        }
        __syncthreads();

        const u32 aH = smem0 + (u32)(cur * ASZB);
        const u32 aL = smem0 + 2 * ASZB + (u32)(cur * ASZB);
        const u32 bB = smem0 + 4 * ASZB + (u32)(cur * BSZB);
#pragma unroll
        for (int kk = 0; kk < 32; kk += 16) {
            u32 a_h[2][4];
            u32 a_l[2][4];
            u32 b_f[8][2];
#pragma unroll
            for (int mt = 0; mt < 2; ++mt) {
                int row = warp_m * 32 + mt * 16 + (lane & 15);
                u32 off = (u32)((row * ASTRIDE + kk + (lane >> 4) * 8) * 2);
                ldsm_x4(a_h[mt], aH + off);
                if (useAl) {
                    ldsm_x4(a_l[mt], aL + off);
                }
            }
#pragma unroll
            for (int p = 0; p < 4; ++p) {
                int colbase = warp_n * 64 + p * 16;
                int krow = kk + (lane & 7) + ((lane >> 3) & 1) * 8;
                int col = colbase + ((lane >> 4) & 1) * 8;
                u32 off = (u32)((krow * BSTRIDE + col) * 2);
                u32 r[4];
                ldsm_x4t(r, bB + off);
                b_f[2 * p][0] = r[0];
                b_f[2 * p][1] = r[1];
                b_f[2 * p + 1][0] = r[2];
                b_f[2 * p + 1][1] = r[3];
            }
#pragma unroll
            for (int mt = 0; mt < 2; ++mt) {
#pragma unroll
                for (int nt = 0; nt < 8; ++nt) {
                    mma_f16(acc[mt][nt], a_h[mt], b_f[nt]);
                    if (useAl) {
                        mma_f16(acc[mt][nt], a_l[mt], b_f[nt]);
                    }
                }
            }
        }
        __syncthreads();
    }

#pragma unroll
    for (int mt = 0; mt < 2; ++mt) {
#pragma unroll
        for (int nt = 0; nt < 8; ++nt) {
            int r = cRow + warp_m * 32 + mt * 16 + (lane >> 2);
            int c = cCol + warp_n * 64 + nt * 8 + (lane & 3) * 2;
            float v0 = acc[mt][nt][0];
            float v1 = acc[mt][nt][1];
            float v2 = acc[mt][nt][2];
            float v3 = acc[mt][nt][3];
            *(float2*)&C[(size_t)r * N + c] = make_float2(v0, v1);
            *(float2*)&C[(size_t)(r + 8) * N + c] = make_float2(v2, v3);
            if (Ch) {
                float s0 = v0 * hscale;
                float s1 = v1 * hscale;
                float s2 = v2 * hscale;
                float s3 = v3 * hscale;
                __half2 h01 = __floats2half2_rn(s0, s1);
                __half2 h23 = __floats2half2_rn(s2, s3);
                *(__half2*)&Ch[(size_t)r * N + c] = h01;
                *(__half2*)&Ch[(size_t)(r + 8) * N + c] = h23;
                if (Cl) {
                    __half2 l01 = __floats2half2_rn(s0 - __low2float(h01),
                                                    s1 - __high2float(h01));
                    __half2 l23 = __floats2half2_rn(s2 - __low2float(h23),
                                                    s3 - __high2float(h23));
                    *(__half2*)&Cl[(size_t)r * N + c] = l01;
                    *(__half2*)&Cl[(size_t)(r + 8) * N + c] = l23;
                }
            }
        }
    }
}

// ------------- feature kernel -------------
__global__ void feat_kernel() {
    const int wg = (blockIdx.x * blockDim.x + threadIdx.x) >> 5;
    const int lane = threadIdx.x & 31;
    if (wg < TOK * H_) {
        const float* src = g_q + (size_t)wg * 64;
        float x0 = src[lane];
        float x1 = src[lane + 32];
        float m = fmaxf(x0, x1);
#pragma unroll
        for (int o = 16; o; o >>= 1) m = fmaxf(m, __shfl_xor_sync(0xffffffffu, m, o));
        float e0 = __expf(x0 - m);
        float e1 = __expf(x1 - m);
        float s = e0 + e1;
#pragma unroll
        for (int o = 16; o; o >>= 1) s += __shfl_xor_sync(0xffffffffu, s, o);
        float inv = 1.f / s;
        float* dst = g_ql + (size_t)wg * 64;
        dst[lane] = e0 * inv;
        dst[lane + 32] = e1 * inv;
    } else if (wg < TOK * H_ + TOK * HKV) {
        const int r = wg - TOK * H_;
        const float* src = g_kv + (size_t)(r >> 3) * KVD + (r & 7) * 64;
        float x0 = src[lane];
        float x1 = src[lane + 32];
        float m = fmaxf(x0, x1);
#pragma unroll
        for (int o = 16; o; o >>= 1) m = fmaxf(m, __shfl_xor_sync(0xffffffffu, m, o));
        float e0 = __expf(x0 - m);
        float e1 = __expf(x1 - m);
        float s = e0 + e1;
#pragma unroll
        for (int o = 16; o; o >>= 1) s += __shfl_xor_sync(0xffffffffu, s, o);
        float inv = 1.f / s;
        float* dst = g_kl + (size_t)r * 64;
        dst[lane] = e0 * inv;
        dst[lane + 32] = e1 * inv;
        float b0 = (fminf(x0, 0.f) - log1pf(__expf(-fabsf(x0)))) * 0.0625f;
        float b1 = (fminf(x1, 0.f) - log1pf(__expf(-fabsf(x1)))) * 0.0625f;
        float* bd = g_beta + (size_t)r * 64;
        bd[lane] = b0;
        bd[lane + 32] = b1;
    }
}

// --------- delta stage 1 (grid = 1024) ---------
__global__ void delta_stage1() {
    extern __shared__ float sm[];
    float* Kc = sm;
    float* W = Kc + 64 * PAD;
    float* U = W + 64 * PAD;
    float* L = U + 64 * PAD;
    float* Q = L + 64 * PAD;

    const int tid = threadIdx.x;
    const int blk = blockIdx.x;
    const int bh = blk >> 4;
    const int ch = blk & 15;
    const int b = bh >> 5;
    const int h = bh & 31;
    const int hkv = h >> 2;
    const int e = tid & 63;
    const int r0 = (tid >> 6) * 8;
    const int n0 = ch * CHUNK;

    for (int idx = tid; idx < 4096; idx += 512) {
        int c = idx >> 6;
        int d = idx & 63;
        int t = b * N_ + n0 + c;
        float kv = g_kl[(size_t)t * KDIM + hkv * 64 + d];
        float bt = g_beta[(size_t)t * KDIM + hkv * 64 + d];
        float vv = g_kv[(size_t)t * KVD + 512 + hkv * 64 + d];
        Kc[c * PAD + d] = kv;
        W[c * PAD + d] = kv * bt;
        U[c * PAD + d] = vv * bt;
        Q[c * PAD + d] = g_ql[(size_t)t * QDIM + h * 64 + d];
    }
    __syncthreads();

    {
        float acc[8];
#pragma unroll
        for (int i = 0; i < 8; ++i) acc[i] = 0.f;
        for (int d = 0; d < 64; ++d) {
            float kb = Kc[e * PAD + d];
#pragma unroll
            for (int i = 0; i < 8; ++i) acc[i] += W[(r0 + i) * PAD + d] * kb;
        }
#pragma unroll
        for (int i = 0; i < 8; ++i) {
            L[(r0 + i) * PAD + e] = (e < r0 + i) ? acc[i] : 0.f;
        }
    }
    __syncthreads();

    for (int j = 0; j < 63; ++j) {
        float uj = U[j * PAD + e];
        float wj = W[j * PAD + e];
        for (int i = j + 1 + (tid >> 6); i < 64; i += 8) {
            float lij = L[i * PAD + j];
            U[i * PAD + e] -= lij * uj;
            W[i * PAD + e] -= lij * wj;
        }
        __syncthreads();
    }

    {
        float acc[8];
#pragma unroll
        for (int i = 0; i < 8; ++i) acc[i] = 0.f;
        for (int d = 0; d < 64; ++d) {
            float kb = Kc[e * PAD + d];
#pragma unroll
            for (int i = 0; i < 8; ++i) acc[i] += Q[(r0 + i) * PAD + d] * kb;
        }
        float* Ao = g_A + (size_t)blk * 4096;
#pragma unroll
        for (int i = 0; i < 8; ++i) {
            Ao[(r0 + i) * 64 + e] = (e <= r0 + i) ? acc[i] : 0.f;
        }
    }
    {
        float* Wo_ = g_W + (size_t)blk * 4096;
        float* Uo_ = g_U + (size_t)blk * 4096;
#pragma unroll
        for (int i = 0; i < 8; ++i) {
            Wo_[(r0 + i) * 64 + e] = W[(r0 + i) * PAD + e];
            Uo_[(r0 + i) * 64 + e] = U[(r0 + i) * PAD + e];
        }
    }
}

// --------------- mma base causal attention, SINGLE pass, fp16 operands -----------
#define QST 72
#define EST 68
__global__ void __launch_bounds__(256) base_attn_mma(float* __restrict__ attnw) {
    extern __shared__ char smc[];
    __half* Qh = (__half*)smc;
    __half* Ql = Qh + 64 * QST;
    __half* Kt = Ql + 64 * QST;
    __half* Vt = Kt + 64 * QST;
    float* Et = (float*)(Vt + 64 * QST);
    float* rbuf = Et + 64 * EST;

    const int it = blockIdx.x;
    const int bh = blockIdx.y;
    const int b = bh >> 5;
    const int h = bh & 31;
    const int hkv = h >> 2;
    const int tid = threadIdx.x;
    const int lane = tid & 31;
    const int wid = tid >> 5;
    const int warp_m = wid & 3;
    const int warp_n = wid >> 2;
    const int m0 = warp_m * 16;
    const int jn0 = warp_n * 32;

    u32 sQh = (u32)__cvta_generic_to_shared(Qh);
    u32 sQl = (u32)__cvta_generic_to_shared(Ql);
    u32 sKt = (u32)__cvta_generic_to_shared(Kt);
    u32 sVt = (u32)__cvta_generic_to_shared(Vt);

    for (int idx = tid; idx < 512; idx += 256) {
        int r = idx >> 3;
        int d = (idx & 7) * 8;
        size_t gp = (size_t)(b * N_ + it * 64 + r) * QDIM + h * 64 + d;
        *(uint4*)&Qh[r * QST + d] = *(const uint4*)&g_q16h[gp];
        *(uint4*)&Ql[r * QST + d] = *(const uint4*)&g_q16l[gp];
    }
    __syncthreads();

    u32 qa_h[4][4];
    u32 qa_l[4][4];
#pragma unroll
    for (int ks = 0; ks < 4; ++ks) {
        u32 off = (u32)(((m0 + (lane & 15)) * QST + ks * 16 + (lane >> 4) * 8) * 2);
        ldsm_x4(qa_h[ks], sQh + off);
        ldsm_x4(qa_l[ks], sQl + off);
    }

    const int r_in0 = m0 + (lane >> 2);
    const int gr0 = it * 64 + r_in0;
    const int gr1 = gr0 + 8;

    float o[8][4];
#pragma unroll
    for (int nt = 0; nt < 8; ++nt) {
#pragma unroll
        for (int i = 0; i < 4; ++i) o[nt][i] = 0.f;
    }
    float rs0 = 0.f;
    float rs1 = 0.f;

    for (int jt = 0; jt <= it; ++jt) {
        __syncthreads();
        for (int idx = tid; idx < 512; idx += 256) {
            int r = idx >> 3;
            int d = (idx & 7) * 8;
            const __half* kvrow = g_kv16 + (size_t)(b * N_ + jt * 64 + r) * KVD + hkv * 64;
            *(uint4*)&Kt[r * QST + d] = *(const uint4*)(kvrow + d);
            *(uint4*)&Vt[r * QST + d] = *(const uint4*)(kvrow + 512 + d);
        }
        __syncthreads();

        float c[4][4];
#pragma unroll
        for (int nt = 0; nt < 4; ++nt) {
#pragma unroll
            for (int i = 0; i < 4; ++i) c[nt][i] = 0.f;
        }
#pragma unroll
        for (int ks = 0; ks < 4; ++ks) {
#pragma unroll
            for (int np = 0; np < 2; ++np) {
                u32 bf[4];
                u32 row = (u32)(jn0 + np * 16 + ((lane >> 4) & 1) * 8 + (lane & 7));
                u32 off = (u32)((row * QST + ks * 16 + ((lane >> 3) & 1) * 8) * 2);
                ldsm_x4(bf, sKt + off);
                mma_f16(c[2 * np], qa_h[ks], bf);
                mma_f16(c[2 * np], qa_l[ks], bf);
                mma_f16(c[2 * np + 1], qa_h[ks], bf + 2);
                mma_f16(c[2 * np + 1], qa_l[ks], bf + 2);
            }
        }

        const bool diag = (jt == it);
#pragma unroll
        for (int nt = 0; nt < 4; ++nt) {
            int col = jn0 + nt * 8 + (lane & 3) * 2;
            int gc = jt * 64 + col;
            float e00 = (!diag || gc <= gr0) ? fexp(c[nt][0] - 4.f) : 0.f;
            float e01 = (!diag || gc + 1 <= gr0) ? fexp(c[nt][1] - 4.f) : 0.f;
            float e10 = (!diag || gc <= gr1) ? fexp(c[nt][2] - 4.f) : 0.f;
            float e11 = (!diag || gc + 1 <= gr1) ? fexp(c[nt][3] - 4.f) : 0.f;
            rs0 += e00 + e01;
            rs1 += e10 + e11;
            c[nt][0] = e00;
            c[nt][1] = e01;
            c[nt][2] = e10;
            c[nt][3] = e11;
            Et[r_in0 * EST + col] = e00;
            Et[r_in0 * EST + col + 1] = e01;
            Et[(r_in0 + 8) * EST + col] = e10;
            Et[(r_in0 + 8) * EST + col + 1] = e11;
        }

        u32 pa[2][4];
#pragma unroll
        for (int kp = 0; kp < 2; ++kp) {
            pa[kp][0] = packh2(c[2 * kp][0], c[2 * kp][1]);
            pa[kp][1] = packh2(c[2 * kp][2], c[2 * kp][3]);
            pa[kp][2] = packh2(c[2 * kp + 1][0], c[2 * kp + 1][1]);
            pa[kp][3] = packh2(c[2 * kp + 1][2], c[2 * kp + 1][3]);
        }
#pragma unroll
        for (int kp = 0; kp < 2; ++kp) {
#pragma unroll
            for (int dp = 0; dp < 4; ++dp) {
                u32 bf[4];
                u32 krow = (u32)(jn0 + kp * 16 + (lane & 7) + ((lane >> 3) & 1) * 8);
                u32 off = (u32)((krow * QST + dp * 16 + ((lane >> 4) & 1) * 8) * 2);
                ldsm_x4t(bf, sVt + off);
                mma_f16(o[2 * dp], pa[kp], bf);
                mma_f16(o[2 * dp + 1], pa[kp], bf + 2);
            }
        }

        __syncthreads();
        if (attnw) {
#pragma unroll
            for (int rr = 0; rr < 4; ++rr) {
                int r = rr * 16 + (tid >> 4);
                int d = (tid & 15) * 4;
                *(float4*)&attnw[((size_t)bh * N_ + it * 64 + r) * N_ + jt * 64 + d] =
                    *(float4*)&Et[r * EST + d];
            }
        }
    }

    if (attnw) {
        float4 z4 = make_float4(0.f, 0.f, 0.f, 0.f);
        for (int jt = it + 1; jt < 16; ++jt) {
#pragma unroll
            for (int rr = 0; rr < 4; ++rr) {
                int r = rr * 16 + (tid >> 4);
                int d = (tid & 15) * 4;
                *(float4*)&attnw[((size_t)bh * N_ + it * 64 + r) * N_ + jt * 64 + d] = z4;
            }
        }
    }

    rs0 += __shfl_xor_sync(0xffffffffu, rs0, 1);
    rs0 += __shfl_xor_sync(0xffffffffu, rs0, 2);
    rs1 += __shfl_xor_sync(0xffffffffu, rs1, 1);
    rs1 += __shfl_xor_sync(0xffffffffu, rs1, 2);
    if ((lane & 3) == 0) {
        rbuf[warp_n * 64 + r_in0] = rs0;
        rbuf[warp_n * 64 + r_in0 + 8] = rs1;
    }
    __syncthreads();
    if (tid < 64) {
        float iv = 1.f / (rbuf[tid] + rbuf[64 + tid]);
        rbuf[tid] = iv;
        g_inv[(size_t)bh * N_ + it * 64 + tid] = iv;
    }
    __syncthreads();
    const float inv0 = rbuf[r_in0];
    const float inv1 = rbuf[r_in0 + 8];

    __syncthreads();
    if (warp_n == 1) {
#pragma unroll
        for (int nt = 0; nt < 8; ++nt) {
            int d = nt * 8 + (lane & 3) * 2;
            Et[r_in0 * EST + d] = o[nt][0];
            Et[r_in0 * EST + d + 1] = o[nt][1];
            Et[(r_in0 + 8) * EST + d] = o[nt][2];
            Et[(r_in0 + 8) * EST + d + 1] = o[nt][3];
        }
    }
    __syncthreads();
    if (warp_n == 0) {
#pragma unroll
        for (int nt = 0; nt < 8; ++nt) {
            int d = nt * 8 + (lane & 3) * 2;
            float v00 = (o[nt][0] + Et[r_in0 * EST + d]) * inv0;
            float v01 = (o[nt][1] + Et[r_in0 * EST + d + 1]) * inv0;
            float v10 = (o[nt][2] + Et[(r_in0 + 8) * EST + d]) * inv1;
            float v11 = (o[nt][3] + Et[(r_in0 + 8) * EST + d + 1]) * inv1;
            size_t p0 = (size_t)(b * N_ + it * 64 + r_in0) * QDIM + h * 64 + d;
            size_t p1 = (size_t)(b * N_ + it * 64 + r_in0 + 8) * QDIM + h * 64 + d;
            *(float2*)&g_obase[p0] = make_float2(v00, v01);
            *(float2*)&g_obase[p1] = make_float2(v10, v11);
        }
    }
}

// --------- renormalize attnw rows by g_inv (coalesced float4) ---------
__global__ void renorm_attn(float* __restrict__ attnw) {
    const int i = blockIdx.x;
    const int bh = blockIdx.y;
    const float iv = g_inv[(size_t)bh * N_ + i];
    float4* row = (float4*)&attnw[((size_t)bh * N_ + i) * N_];
    float4 v = row[threadIdx.x];
    v.x *= iv;
    v.y *= iv;
    v.z *= iv;
    v.w *= iv;
    row[threadIdx.x] = v;
}

// --------- delta stage 2 (grid = 64) ---------
__global__ void delta_stage2() {
    extern __shared__ float sm[];
    float* S = sm;
    float* W = S + 64 * PAD;
    float* U = W + 64 * PAD;
    float* A = U + 64 * PAD;
    float* Q = A + 64 * PAD;
    float* Kc = Q + 64 * PAD;

    const int tid = threadIdx.x;
    const int bh = blockIdx.x;
    const int b = bh >> 5;
    const int h = bh & 31;
    const int hkv = h >> 2;
    const int e = tid & 63;
    const int r0 = (tid >> 6) * 8;

    for (int idx = tid; idx < 4096; idx += 512) {
        S[(idx >> 6) * PAD + (idx & 63)] = 0.f;
    }
    __syncthreads();

    for (int ch = 0; ch < NC; ++ch) {
        const int n0 = ch * CHUNK;
        const size_t base = (size_t)(bh * NC + ch) * 4096;
        for (int idx = tid; idx < 4096; idx += 512) {
            int c = idx >> 6;
            int d = idx & 63;
            int t = b * N_ + n0 + c;
            W[c * PAD + d] = g_W[base + idx];
            U[c * PAD + d] = g_U[base + idx];
            A[c * PAD + d] = g_A[base + idx];
            Q[c * PAD + d] = g_ql[(size_t)t * QDIM + h * 64 + d];
            Kc[c * PAD + d] = g_kl[(size_t)t * KDIM + hkv * 64 + d];
        }
        __syncthreads();

        {
            float acc[8];
#pragma unroll
            for (int i = 0; i < 8; ++i) acc[i] = 0.f;
            for (int d = 0; d < 64; ++d) {
                float s = S[d * PAD + e];
#pragma unroll
                for (int i = 0; i < 8; ++i) acc[i] += W[(r0 + i) * PAD + d] * s;
            }
#pragma unroll
            for (int i = 0; i < 8; ++i) U[(r0 + i) * PAD + e] -= acc[i];
        }
        __syncthreads();

        {
            float acc[8];
#pragma unroll
            for (int i = 0; i < 8; ++i) acc[i] = 0.f;
            for (int d = 0; d < 64; ++d) {
                float s = S[d * PAD + e];
#pragma unroll
                for (int i = 0; i < 8; ++i) acc[i] += Q[(r0 + i) * PAD + d] * s;
            }
            for (int j = 0; j < 64; ++j) {
                float u = U[j * PAD + e];
#pragma unroll
                for (int i = 0; i < 8; ++i) acc[i] += A[(r0 + i) * PAD + j] * u;
            }
#pragma unroll
            for (int i = 0; i < 8; ++i) {
                g_olin[(size_t)(b * N_ + n0 + r0 + i) * QDIM + h * 64 + e] = acc[i];
            }
        }
        __syncthreads();

        {
            float acc[8];
#pragma unroll
            for (int i = 0; i < 8; ++i) acc[i] = 0.f;
            for (int c = 0; c < 64; ++c) {
                float u = U[c * PAD + e];
#pragma unroll
                for (int i = 0; i < 8; ++i) acc[i] += Kc[c * PAD + r0 + i] * u;
            }
#pragma unroll
            for (int i = 0; i < 8; ++i) S[(r0 + i) * PAD + e] += acc[i];
        }
        __syncthreads();
    }
}

// --------- mix + fp16 convert (single output; out-proj uses single-A) -----------
__global__ void split_mix() {
    int i = blockIdx.x * 256 + threadIdx.x;
    if (i < TOK * QDIM) {
        float x = 0.5f * g_obase[i] + 0.5f * g_olin[i];
        g_oxh[i] = __float2half(x);
    }
}

// ------------------------------------ launch -------------------------------------
extern "C" void kernel_launch(void* const* d_in, const int* in_sizes, int n_in,
                              void* d_out, int out_size) {
    const float* hs = (const float*)d_in[0];
    const float* Wq = (const float*)d_in[1];
    const float* Wk = (const float*)d_in[2];
    const float* Wv = (const float*)d_in[3];
    const float* Wo = (const float*)d_in[4];
    float* out = (float*)d_out;

    const size_t out_elems = (size_t)TOK * QDIM;
    const size_t attn_elems = (size_t)B_ * H_ * N_ * N_;
    float* attnw = ((size_t)out_size >= out_elems + attn_elems) ? (out + out_elems)
                                                                : (float*)0;

    float* qp;
    float* kvp;
    __half* hshp; __half* hslp;
    __half* wqp;
    __half* wkvp;
    __half* wop;
    __half* oxhp;
    __half* q16hp; __half* q16lp; __half* kv16p;
    cudaGetSymbolAddress((void**)&qp, g_q);
    cudaGetSymbolAddress((void**)&kvp, g_kv);
    cudaGetSymbolAddress((void**)&hshp, g_hsh);
    cudaGetSymbolAddress((void**)&hslp, g_hsl);
    cudaGetSymbolAddress((void**)&wqp, g_wq);
    cudaGetSymbolAddress((void**)&wkvp, g_wkv);
    cudaGetSymbolAddress((void**)&wop, g_wo);
    cudaGetSymbolAddress((void**)&oxhp, g_oxh);
    cudaGetSymbolAddress((void**)&q16hp, g_q16h);
    cudaGetSymbolAddress((void**)&q16lp, g_q16l);
    cudaGetSymbolAddress((void**)&kv16p, g_kv16);

    cudaFuncSetAttribute(hgemm, cudaFuncAttributeMaxDynamicSharedMemorySize, HG_SMEM);
    cudaFuncSetAttribute(delta_stage1, cudaFuncAttributeMaxDynamicSharedMemorySize,
                         5 * 64 * PAD * (int)sizeof(float));
    cudaFuncSetAttribute(delta_stage2, cudaFuncAttributeMaxDynamicSharedMemorySize,
                         6 * 64 * PAD * (int)sizeof(float));
    const int ba_smem = 4 * 64 * QST * 2 + 64 * EST * 4 + 128 * 4;
    cudaFuncSetAttribute(base_attn_mma, cudaFuncAttributeMaxDynamicSharedMemorySize,
                         ba_smem);

    // 1: fused split/convert
    {
        const int total = SEG0 + SEG1 + SEG2 + SEG3 + SEG4;
        split_all<<<(total + 255) / 256, 256>>>(hs, Wq, Wk, Wv, Wo);
    }

    // 2-3: projections (+ fp16 side outputs for base attention), split-A
    hgemm<<<dim3(QDIM / 128, TOK / 128), 256, HG_SMEM>>>(
        hshp, hslp, wqp, qp, q16hp, q16lp, 0.125f, QDIM, HID, 1);
    hgemm<<<dim3(KVD / 128, TOK / 128), 256, HG_SMEM>>>(
        hshp, hslp, wkvp, kvp, kv16p, (__half*)0, 1.0f, KVD, HID, 1);

    // 4: feature maps + gate
    {
        const int total_warps = TOK * H_ + TOK * HKV;
        const int blocks = (total_warps * 32 + 255) / 256;
        feat_kernel<<<blocks, 256>>>();
    }

    // 5: delta stage 1
    delta_stage1<<<B_ * H_ * NC, 512, 5 * 64 * PAD * sizeof(float)>>>();

    // 6: base attention (single pass, fp16 operands)
    base_attn_mma<<<dim3(16, B_ * H_), 256, ba_smem>>>(attnw);

    // 7: renormalize attention weights
    if (attnw) {
        renorm_attn<<<dim3(N_, B_ * H_), 256>>>(attnw);
    }

    // 8: delta stage 2
    delta_stage2<<<B_ * H_, 512, 6 * 64 * PAD * sizeof(float)>>>();

    // 9: mix + fp16 convert
    split_mix<<<(TOK * QDIM + 255) / 256, 256>>>();

    // 10: output projection (single-A fp16)
    hgemm<<<dim3(HID / 128, TOK / 128), 256, HG_SMEM>>>(
        oxhp, (__half*)0, wop, out, (__half*)0, (__half*)0, 1.0f, HID, QDIM, 0);
}